// round 16
// baseline (speedup 1.0000x reference)
#include <cuda_runtime.h>
#include <cstdint>

// x: (128, 1, 28, 28) f32  -> out: (128, 785, 28, 28) f32
// out[b,0,:]   = new_pv(x[b])
// out[b,1+i,:] = new_e(x[b,i]) at flat pos i, else 0
//
// R9-family converged design, wave-count variant:
//  - one thread stores 16 float4s at 4KB (256-f4) stride -> every warp STG.128
//    covers a contiguous 512B span (perfect coalescing)
//  - block covers 64KB contiguous; grid (38,128)=4864 CTAs (~4 waves vs ~8)
//  - (channel, offset) tracked incrementally; single div in the prologue
//  - __stcs streaming stores (output is write-once, never re-read)
static constexpr unsigned B     = 128;
static constexpr unsigned HW    = 784;               // floats per channel
static constexpr unsigned HW4   = 196;               // float4 per channel
static constexpr unsigned CPB4  = 785u * 196u;       // float4 per batch = 153,860
static constexpr unsigned F4_PER_BLOCK = 4096;       // 64KB contiguous per block
static constexpr unsigned ITERS = 16;                // 4096 / 256
static constexpr unsigned STEP  = 256;               // threads per block

__device__ __forceinline__ float pv_map(float pv) {
    const float eps = 0.1f;
    bool low  = pv < eps;
    bool high = pv > 1.0f - eps;
    return low  ? (pv + eps) * 0.5f
         : high ? (pv + (1.0f - eps)) * 0.5f
         :        pv;
}

__device__ __forceinline__ float e_map(float pv) {
    const float eps = 0.1f;
    bool low  = pv < eps;
    bool high = pv > 1.0f - eps;
    return low  ? (eps + pv) * 0.5f
         : high ? ((1.0f - pv) + eps) * 0.5f
         :        eps;
}

__global__ void fused_kernel(const float* __restrict__ x,
                             float4* __restrict__ out) {
    const unsigned b = blockIdx.y;
    unsigned j4 = blockIdx.x * F4_PER_BLOCK + threadIdx.x;  // f4 index in batch

    const float* xb = x + b * HW;
    float4* ob = out + (unsigned long long)b * (unsigned long long)CPB4;

    // Prologue: one division, then incremental updates.
    unsigned c  = j4 / HW4;               // channel
    unsigned r4 = j4 - c * HW4;           // f4 offset within channel

    #pragma unroll
    for (unsigned j = 0; j < ITERS; j++) {
        if (j4 < CPB4) {
            unsigned d = c - 1u - 4u * r4;     // diag offset in window (wraps)

            float4 v = make_float4(0.f, 0.f, 0.f, 0.f);
            if (c == 0u) {
                // channel 0: pv map of 4 contiguous inputs (only block x==0)
                float4 xv = reinterpret_cast<const float4*>(xb)[r4];
                v.x = pv_map(xv.x);
                v.y = pv_map(xv.y);
                v.z = pv_map(xv.z);
                v.w = pv_map(xv.w);
            } else if (d < 4u) {
                // diagonal element lands in this float4 (1 in 196)
                float ev = e_map(xb[c - 1u]);
                v.x = (d == 0u) ? ev : 0.f;
                v.y = (d == 1u) ? ev : 0.f;
                v.z = (d == 2u) ? ev : 0.f;
                v.w = (d == 3u) ? ev : 0.f;
            }
            __stcs(ob + j4, v);                // streaming store, evict-first
        }
        // Advance by 256 f4: c += 1, r4 += 60, with at most one wrap.
        j4 += STEP;
        c  += 1u;
        r4 += STEP - HW4;                      // +60
        if (r4 >= HW4) { r4 -= HW4; c += 1u; }
    }
}

extern "C" void kernel_launch(void* const* d_in, const int* in_sizes, int n_in,
                              void* d_out, int out_size) {
    const float* x = (const float*)d_in[0];
    float4* out = (float4*)d_out;

    const int threads = 256;
    dim3 grid((CPB4 + F4_PER_BLOCK - 1) / F4_PER_BLOCK, B);  // (38, 128)
    fused_kernel<<<grid, threads>>>(x, out);
}

// round 17
// speedup vs baseline: 1.0510x; 1.0510x over previous
#include <cuda_runtime.h>
#include <cstdint>

// x: (128, 1, 28, 28) f32  -> out: (128, 785, 28, 28) f32
// out[b,0,:]   = new_pv(x[b])
// out[b,1+i,:] = new_e(x[b,i]) at flat pos i, else 0
//
// FINAL converged design (best measured: 45.66us kernel = ~6.9 TB/s store
// throughput, the path-independent LTS/store-path ceiling on sm_100a):
//  - one thread stores 8 float4s at 4KB (256-f4) stride -> every warp STG.128
//    covers a contiguous 512B span (perfect coalescing)
//  - block covers 32KB contiguous; grid (76,128)=9728 CTAs (~8 waves; fewer
//    waves measured WORSE -- scheduler interleaving beats residency)
//  - (channel, offset) tracked incrementally; single div in the prologue
//  - __stcs streaming stores (output is write-once, never re-read)
static constexpr unsigned B     = 128;
static constexpr unsigned HW    = 784;               // floats per channel
static constexpr unsigned HW4   = 196;               // float4 per channel
static constexpr unsigned CPB4  = 785u * 196u;       // float4 per batch = 153,860
static constexpr unsigned F4_PER_BLOCK = 2048;       // 32KB contiguous per block
static constexpr unsigned ITERS = 8;                 // 2048 / 256
static constexpr unsigned STEP  = 256;               // threads per block

__device__ __forceinline__ float pv_map(float pv) {
    const float eps = 0.1f;
    bool low  = pv < eps;
    bool high = pv > 1.0f - eps;
    return low  ? (pv + eps) * 0.5f
         : high ? (pv + (1.0f - eps)) * 0.5f
         :        pv;
}

__device__ __forceinline__ float e_map(float pv) {
    const float eps = 0.1f;
    bool low  = pv < eps;
    bool high = pv > 1.0f - eps;
    return low  ? (eps + pv) * 0.5f
         : high ? ((1.0f - pv) + eps) * 0.5f
         :        eps;
}

__global__ void fused_kernel(const float* __restrict__ x,
                             float4* __restrict__ out) {
    const unsigned b = blockIdx.y;
    unsigned j4 = blockIdx.x * F4_PER_BLOCK + threadIdx.x;  // f4 index in batch

    const float* xb = x + b * HW;
    float4* ob = out + (unsigned long long)b * (unsigned long long)CPB4;

    // Prologue: one division, then incremental updates.
    unsigned c  = j4 / HW4;               // channel
    unsigned r4 = j4 - c * HW4;           // f4 offset within channel

    #pragma unroll
    for (unsigned j = 0; j < ITERS; j++) {
        if (j4 < CPB4) {
            unsigned d = c - 1u - 4u * r4;     // diag offset in window (wraps)

            float4 v = make_float4(0.f, 0.f, 0.f, 0.f);
            if (c == 0u) {
                // channel 0: pv map of 4 contiguous inputs (only block x==0)
                float4 xv = reinterpret_cast<const float4*>(xb)[r4];
                v.x = pv_map(xv.x);
                v.y = pv_map(xv.y);
                v.z = pv_map(xv.z);
                v.w = pv_map(xv.w);
            } else if (d < 4u) {
                // diagonal element lands in this float4 (1 in 196)
                float ev = e_map(xb[c - 1u]);
                v.x = (d == 0u) ? ev : 0.f;
                v.y = (d == 1u) ? ev : 0.f;
                v.z = (d == 2u) ? ev : 0.f;
                v.w = (d == 3u) ? ev : 0.f;
            }
            __stcs(ob + j4, v);                // streaming store, evict-first
        }
        // Advance by 256 f4: c += 1, r4 += 60, with at most one wrap.
        j4 += STEP;
        c  += 1u;
        r4 += STEP - HW4;                      // +60
        if (r4 >= HW4) { r4 -= HW4; c += 1u; }
    }
}

extern "C" void kernel_launch(void* const* d_in, const int* in_sizes, int n_in,
                              void* d_out, int out_size) {
    const float* x = (const float*)d_in[0];
    float4* out = (float4*)d_out;

    const int threads = 256;
    dim3 grid((CPB4 + F4_PER_BLOCK - 1) / F4_PER_BLOCK, B);  // (76, 128)
    fused_kernel<<<grid, threads>>>(x, out);
}